// round 12
// baseline (speedup 1.0000x reference)
#include <cuda_runtime.h>
#include <cuda_fp16.h>
#include <cstdint>

#define NN   50000
#define EE   1600000
#define FIN  512
#define F1   64        // H1*C1
#define NH1  8
#define C2   40
#define NBLK 196       // ceil(NN/256)
#define GEMMB 391      // ceil(NN/128)
#define FULLM 0xffffffffu
#define LOG2E 1.4426950408889634f

// ------------------------- scratch (static device memory; no allocs allowed)
__device__ __half g_h1h[NN * F1];      // layer1 features, fp16 (gather payload)
__device__ __half g_as1h[NN * NH1];    // alpha_src1 * log2e, fp16
__device__ __half g_ad1h[NN * NH1];    // alpha_dst1 * log2e, fp16
__device__ __half g_h2h[NN * C2];      // layer2 linear out, fp16 (gather payload)
__device__ float  g_as2[NN];
__device__ float  g_ad2[NN];
__device__ int    g_deg[NN];           // zero at entry of every call (reset by k_scan1)
__device__ int    g_rowptr[NN + 1];
__device__ int    g_cursor[NN];
__device__ int    g_col[EE];

__device__ __forceinline__ float leaky(float v) { return v > 0.f ? v : 0.2f * v; }

__device__ __forceinline__ uint32_t f2tf(float f) {
    uint32_t u;
    asm("cvt.rna.tf32.f32 %0, %1;" : "=r"(u) : "f"(f));
    return u;
}

__device__ __forceinline__ void mma_tf32(float* d, const uint32_t* a, const uint32_t* b) {
    asm volatile(
        "mma.sync.aligned.m16n8k8.row.col.f32.tf32.tf32.f32 "
        "{%0,%1,%2,%3}, {%4,%5,%6,%7}, {%8,%9}, {%0,%1,%2,%3};"
        : "+f"(d[0]), "+f"(d[1]), "+f"(d[2]), "+f"(d[3])
        : "r"(a[0]), "r"(a[1]), "r"(a[2]), "r"(a[3]), "r"(b[0]), "r"(b[1]));
}

__device__ __forceinline__ __half2 h2ex2(__half2 x) {
    __half2 r;
    asm("ex2.approx.f16x2 %0, %1;"
        : "=r"(*(uint32_t*)&r) : "r"(*(uint32_t*)&x));
    return r;
}
__device__ __forceinline__ __half2 u2h2(uint32_t u) { return *(__half2*)&u; }

// ------------------------- (1) degree histogram
__global__ void k_hist(const int* __restrict__ dst) {
    int e = blockIdx.x * blockDim.x + threadIdx.x;
    if (e < EE) atomicAdd(&g_deg[dst[e]], 1);
}

// ------------------------- (2) single-launch scan: rowptr/cursor + g_deg reset
// block b redundantly sums all degrees before its 256 nodes (coalesced).
__global__ __launch_bounds__(256) void k_scan1() {
    __shared__ int red[256];
    __shared__ int sm[256];
    __shared__ int sbase;
    const int b = blockIdx.x, t = threadIdx.x;
    const int base = b * 256;

    int pre = 0;
    for (int i = t; i < base; i += 256) pre += g_deg[i];
    red[t] = pre;
    __syncthreads();
#pragma unroll
    for (int off = 128; off > 0; off >>= 1) {
        if (t < off) red[t] += red[t + off];
        __syncthreads();
    }
    if (t == 0) sbase = red[0];

    const int i = base + t;
    const int d = (i < NN) ? g_deg[i] : 0;
    sm[t] = d;
    __syncthreads();
#pragma unroll
    for (int off = 1; off < 256; off <<= 1) {
        int v = (t >= off) ? sm[t - off] : 0;
        __syncthreads();
        sm[t] += v;
        __syncthreads();
    }
    const int bb = sbase;
    if (i < NN) {
        int rp = bb + sm[t] - d;
        g_rowptr[i] = rp;
        g_cursor[i] = rp;
        g_deg[i] = 0;                       // restore invariant for next call
    }
    if (b == NBLK - 1 && t == 255) g_rowptr[NN] = bb + sm[255];
}

// ------------------------- (3) fused: GEMM1 (tf32 TC + att coeffs) || edge scatter
__global__ __launch_bounds__(256) void k_fused(const float* __restrict__ x,
                                               const float* __restrict__ W1,
                                               const float* __restrict__ attS,
                                               const float* __restrict__ attD,
                                               const int* __restrict__ src,
                                               const int* __restrict__ dst) {
    if (blockIdx.x >= GEMMB) {
        // ---- scatter branch (independent of GEMM)
        int e = (blockIdx.x - GEMMB) * 256 + threadIdx.x;
        if (e < EE) {
            int d = dst[e];
            int p = atomicAdd(&g_cursor[d], 1);
            g_col[p] = src[e];
        }
        return;
    }

    // ---- GEMM branch
    __shared__ float sA[128][36];
    __shared__ float sB[32][72];
    __shared__ float sAs[64], sAd[64];

    const int t    = threadIdx.x;
    const int wid  = t >> 5;
    const int lane = t & 31;
    const int m0   = blockIdx.x * 128;
    const int warp_m = (wid >> 1) * 32;
    const int warp_n = (wid & 1) * 32;
    if (t < 64) { sAs[t] = attS[t]; sAd[t] = attD[t]; }

    float acc[2][4][4];
#pragma unroll
    for (int mi = 0; mi < 2; mi++)
#pragma unroll
        for (int ni = 0; ni < 4; ni++)
#pragma unroll
            for (int e = 0; e < 4; e++) acc[mi][ni][e] = 0.f;

    const int r = lane >> 2;
    const int c = lane & 3;
    const int arow = t >> 3;
    const int acol = (t & 7) * 4;

    for (int kc = 0; kc < FIN; kc += 32) {
#pragma unroll
        for (int i = 0; i < 4; i++) {
            int row = i * 32 + arow;
            int gm  = m0 + row;
            float4 v = (gm < NN) ? *(const float4*)&x[(long)gm * FIN + kc + acol]
                                 : make_float4(0.f, 0.f, 0.f, 0.f);
            float4 tv;
            tv.x = __uint_as_float(f2tf(v.x));
            tv.y = __uint_as_float(f2tf(v.y));
            tv.z = __uint_as_float(f2tf(v.z));
            tv.w = __uint_as_float(f2tf(v.w));
            *(float4*)&sA[row][acol] = tv;
        }
#pragma unroll
        for (int i = 0; i < 2; i++) {
            int f   = t + i * 256;
            int row = f >> 4;
            int c4  = (f & 15) * 4;
            float4 v = *(const float4*)&W1[(kc + row) * F1 + c4];
            float4 tv;
            tv.x = __uint_as_float(f2tf(v.x));
            tv.y = __uint_as_float(f2tf(v.y));
            tv.z = __uint_as_float(f2tf(v.z));
            tv.w = __uint_as_float(f2tf(v.w));
            *(float4*)&sB[row][c4] = tv;
        }
        __syncthreads();

#pragma unroll
        for (int ks = 0; ks < 4; ks++) {
            const int k0 = ks * 8;
            uint32_t afrag[2][4];
#pragma unroll
            for (int mi = 0; mi < 2; mi++) {
                int mm = warp_m + mi * 16;
                afrag[mi][0] = __float_as_uint(sA[mm + r][k0 + c]);
                afrag[mi][1] = __float_as_uint(sA[mm + r + 8][k0 + c]);
                afrag[mi][2] = __float_as_uint(sA[mm + r][k0 + c + 4]);
                afrag[mi][3] = __float_as_uint(sA[mm + r + 8][k0 + c + 4]);
            }
            uint32_t bfrag[4][2];
#pragma unroll
            for (int ni = 0; ni < 4; ni++) {
                int nn = warp_n + ni * 8;
                bfrag[ni][0] = __float_as_uint(sB[k0 + c][nn + r]);
                bfrag[ni][1] = __float_as_uint(sB[k0 + c + 4][nn + r]);
            }
#pragma unroll
            for (int mi = 0; mi < 2; mi++)
#pragma unroll
                for (int ni = 0; ni < 4; ni++)
                    mma_tf32(acc[mi][ni], afrag[mi], bfrag[ni]);
        }
        __syncthreads();
    }

#pragma unroll
    for (int mi = 0; mi < 2; mi++) {
        int row_g = m0 + warp_m + mi * 16 + r;
        int row_h = row_g + 8;
#pragma unroll
        for (int ni = 0; ni < 4; ni++) {
            int nn = warp_n + ni * 8;
            int col = nn + c * 2;
            if (row_g < NN)
                *(__half2*)&g_h1h[row_g * F1 + col] = __floats2half2_rn(acc[mi][ni][0], acc[mi][ni][1]);
            if (row_h < NN)
                *(__half2*)&g_h1h[row_h * F1 + col] = __floats2half2_rn(acc[mi][ni][2], acc[mi][ni][3]);
            float as0 = sAs[col], as1v = sAs[col + 1];
            float ad0 = sAd[col], ad1v = sAd[col + 1];
            float psg = acc[mi][ni][0] * as0 + acc[mi][ni][1] * as1v;
            float pdg = acc[mi][ni][0] * ad0 + acc[mi][ni][1] * ad1v;
            float psh = acc[mi][ni][2] * as0 + acc[mi][ni][3] * as1v;
            float pdh = acc[mi][ni][2] * ad0 + acc[mi][ni][3] * ad1v;
#pragma unroll
            for (int off = 1; off <= 2; off <<= 1) {
                psg += __shfl_xor_sync(FULLM, psg, off);
                pdg += __shfl_xor_sync(FULLM, pdg, off);
                psh += __shfl_xor_sync(FULLM, psh, off);
                pdh += __shfl_xor_sync(FULLM, pdh, off);
            }
            int h = nn >> 3;
            if (c == 0) {
                if (row_g < NN) {
                    g_as1h[row_g * NH1 + h] = __float2half_rn(psg * LOG2E);
                    g_ad1h[row_g * NH1 + h] = __float2half_rn(pdg * LOG2E);
                }
                if (row_h < NN) {
                    g_as1h[row_h * NH1 + h] = __float2half_rn(psh * LOG2E);
                    g_ad1h[row_h * NH1 + h] = __float2half_rn(pdh * LOG2E);
                }
            }
        }
    }
}

// ------------------------- (4) layer-1 aggregation + fused layer-2 linear/att
// one warp per dst node; 8-wide batched gathers (explicit MLP)
__global__ __launch_bounds__(256) void k_agg1(const float* __restrict__ b1,
                                              const float* __restrict__ W2,
                                              const float* __restrict__ att_s,
                                              const float* __restrict__ att_d) {
    __shared__ float swt[8][8][36];
    __shared__ int   ssrc[8][32];
    __shared__ float sW2[F1 * C2];
    __shared__ float sAs2[C2], sAd2[C2];

    for (int idx = threadIdx.x; idx < F1 * C2; idx += 256) sW2[idx] = W2[idx];
    if (threadIdx.x < C2) {
        sAs2[threadIdx.x] = att_s[threadIdx.x];
        sAd2[threadIdx.x] = att_d[threadIdx.x];
    }
    __syncthreads();

    const int w    = threadIdx.x >> 5;
    const int lane = threadIdx.x & 31;
    const int node = blockIdx.x * 8 + w;
    if (node >= NN) return;
    const int beg   = g_rowptr[node];
    const int deg   = g_rowptr[node + 1] - beg;
    const int total = deg + 1;

    const __half2 k02 = __floats2half2_rn(0.2f, 0.2f);
    int4 adv = *(const int4*)&g_ad1h[node * NH1];
    __half2 adp[4] = { u2h2(adv.x), u2h2(adv.y), u2h2(adv.z), u2h2(adv.w) };

    const int hl = lane >> 2;
    const int c0 = lane * 2;
    float acc0 = 0.f, acc1 = 0.f;
    float ssum[8];
#pragma unroll
    for (int h = 0; h < 8; h++) ssum[h] = 0.f;

    for (int k0 = 0; k0 < total; k0 += 32) {
        int kk  = k0 + lane;
        int lim = min(32, total - k0);
        __syncwarp();
        if (kk < total) {
            int srcn = (kk < deg) ? g_col[beg + kk] : node;
            int4 sv = *(const int4*)&g_as1h[srcn * NH1];
            __half2 sp[4] = { u2h2(sv.x), u2h2(sv.y), u2h2(sv.z), u2h2(sv.w) };
#pragma unroll
            for (int p = 0; p < 4; p++) {
                __half2 l = __hadd2(sp[p], adp[p]);                  // (as+ad)*log2e
                __half2 lk = __hmax2(l, __hmul2(l, k02));            // leaky (exact)
                float2 f = __half22float2(h2ex2(lk));                // exp via ex2
                ssum[2 * p]     += f.x;
                ssum[2 * p + 1] += f.y;
                swt[w][2 * p][lane]     = f.x;
                swt[w][2 * p + 1][lane] = f.y;
            }
            ssrc[w][lane] = srcn;
        }
        __syncwarp();
        // 8-wide batched gather: force 8 independent LDGs in flight
        int j = 0;
        for (; j + 8 <= lim; j += 8) {
            int   sn[8];
            float wt[8];
            float2 pv[8];
#pragma unroll
            for (int q = 0; q < 8; q++) {
                sn[q] = ssrc[w][j + q];
                wt[q] = swt[w][hl][j + q];
            }
#pragma unroll
            for (int q = 0; q < 8; q++)
                pv[q] = __half22float2(*(const __half2*)&g_h1h[sn[q] * F1 + c0]);
#pragma unroll
            for (int q = 0; q < 8; q++) {
                acc0 += wt[q] * pv[q].x;
                acc1 += wt[q] * pv[q].y;
            }
        }
        for (; j < lim; j++) {
            int srcn = ssrc[w][j];
            float wt = swt[w][hl][j];
            float2 hv = __half22float2(*(const __half2*)&g_h1h[srcn * F1 + c0]);
            acc0 += wt * hv.x;
            acc1 += wt * hv.y;
        }
    }
#pragma unroll
    for (int h = 0; h < 8; h++) {
#pragma unroll
        for (int off = 16; off > 0; off >>= 1)
            ssum[h] += __shfl_xor_sync(FULLM, ssum[h], off);
    }
    float myS = 0.f;
#pragma unroll
    for (int h = 0; h < 8; h++)
        if (hl == h) myS = ssum[h];
    float inv = __fdividef(1.0f, myS);

    // x2 row in registers (relu + bias)
    float v0 = fmaxf(acc0 * inv + b1[c0], 0.f);
    float v1 = fmaxf(acc1 * inv + b1[c0 + 1], 0.f);

    // fused layer-2 linear: h2 = x2 @ W2  (+ attention coefficients)
    const int cA = lane;
    const int cB = lane + 32;
    const bool has1 = (lane < 8);
    float a0 = 0.f, a1 = 0.f;
#pragma unroll
    for (int kk = 0; kk < 32; kk++) {
        float x0 = __shfl_sync(FULLM, v0, kk);
        float x1 = __shfl_sync(FULLM, v1, kk);
        a0 += x0 * sW2[(2 * kk) * C2 + cA] + x1 * sW2[(2 * kk + 1) * C2 + cA];
        if (has1)
            a1 += x0 * sW2[(2 * kk) * C2 + cB] + x1 * sW2[(2 * kk + 1) * C2 + cB];
    }
    g_h2h[node * C2 + cA] = __float2half_rn(a0);
    if (has1) g_h2h[node * C2 + cB] = __float2half_rn(a1);

    float ps = a0 * sAs2[cA] + (has1 ? a1 * sAs2[cB] : 0.f);
    float pd = a0 * sAd2[cA] + (has1 ? a1 * sAd2[cB] : 0.f);
#pragma unroll
    for (int off = 16; off > 0; off >>= 1) {
        ps += __shfl_xor_sync(FULLM, ps, off);
        pd += __shfl_xor_sync(FULLM, pd, off);
    }
    if (lane == 0) { g_as2[node] = ps; g_ad2[node] = pd; }
}

// ------------------------- (5) layer-2 aggregation + bias + log_softmax
// one warp per node; 20 lanes own channel PAIRS; 8-wide batched gathers
__global__ __launch_bounds__(256) void k_agg2(const float* __restrict__ b2,
                                              float* __restrict__ out) {
    __shared__ float swt[8][32];
    __shared__ int   ssrc[8][32];
    const int w    = threadIdx.x >> 5;
    const int lane = threadIdx.x & 31;
    const int node = blockIdx.x * 8 + w;
    if (node >= NN) return;
    const int beg   = g_rowptr[node];
    const int deg   = g_rowptr[node + 1] - beg;
    const int total = deg + 1;
    const float adn = g_ad2[node];

    const bool active = (lane < 20);        // channel pair 2*lane, 2*lane+1
    const int cp = lane * 2;
    float acc0 = 0.f, acc1 = 0.f, ssum = 0.f;
    for (int k0 = 0; k0 < total; k0 += 32) {
        int kk  = k0 + lane;
        int lim = min(32, total - k0);
        __syncwarp();
        if (kk < total) {
            int srcn = (kk < deg) ? g_col[beg + kk] : node;
            float wt = __expf(leaky(g_as2[srcn] + adn));
            ssum += wt;
            swt[w][lane]  = wt;
            ssrc[w][lane] = srcn;
        }
        __syncwarp();
        if (active) {
            int j = 0;
            for (; j + 8 <= lim; j += 8) {
                int   sn[8];
                float wt[8];
                float2 pv[8];
#pragma unroll
                for (int q = 0; q < 8; q++) {
                    sn[q] = ssrc[w][j + q];
                    wt[q] = swt[w][j + q];
                }
#pragma unroll
                for (int q = 0; q < 8; q++)
                    pv[q] = __half22float2(*(const __half2*)&g_h2h[sn[q] * C2 + cp]);
#pragma unroll
                for (int q = 0; q < 8; q++) {
                    acc0 += wt[q] * pv[q].x;
                    acc1 += wt[q] * pv[q].y;
                }
            }
            for (; j < lim; j++) {
                int srcn = ssrc[w][j];
                float wt = swt[w][j];
                float2 hv = __half22float2(*(const __half2*)&g_h2h[srcn * C2 + cp]);
                acc0 += wt * hv.x;
                acc1 += wt * hv.y;
            }
        }
    }
#pragma unroll
    for (int off = 16; off > 0; off >>= 1)
        ssum += __shfl_xor_sync(FULLM, ssum, off);
    float inv = __fdividef(1.0f, ssum);

    float o0 = active ? (acc0 * inv + b2[cp])     : -1e30f;
    float o1 = active ? (acc1 * inv + b2[cp + 1]) : -1e30f;

    float mx = fmaxf(o0, o1);
#pragma unroll
    for (int off = 16; off > 0; off >>= 1)
        mx = fmaxf(mx, __shfl_xor_sync(FULLM, mx, off));
    float se = active ? (__expf(o0 - mx) + __expf(o1 - mx)) : 0.f;
#pragma unroll
    for (int off = 16; off > 0; off >>= 1)
        se += __shfl_xor_sync(FULLM, se, off);
    float lse = mx + __logf(se);

    if (active)
        *(float2*)&out[node * C2 + cp] = make_float2(o0 - lse, o1 - lse);
}

// ------------------------- launch: 5 kernels, single stream
extern "C" void kernel_launch(void* const* d_in, const int* in_sizes, int n_in,
                              void* d_out, int out_size) {
    const float* x        = (const float*)d_in[0];
    const int*   ei       = (const int*)d_in[1];
    const float* W1       = (const float*)d_in[2];
    const float* att_src1 = (const float*)d_in[3];
    const float* att_dst1 = (const float*)d_in[4];
    const float* b1       = (const float*)d_in[5];
    const float* W2       = (const float*)d_in[6];
    const float* att_src2 = (const float*)d_in[7];
    const float* att_dst2 = (const float*)d_in[8];
    const float* b2       = (const float*)d_in[9];
    float* out = (float*)d_out;

    const int* src = ei;
    const int* dst = ei + EE;

    k_hist<<<(EE + 255) / 256, 256>>>(dst);                       // (1)
    k_scan1<<<NBLK, 256>>>();                                     // (2)
    k_fused<<<GEMMB + (EE + 255) / 256, 256>>>(x, W1, att_src1,   // (3) gemm || scatter
                                               att_dst1, src, dst);
    k_agg1<<<(NN + 7) / 8, 256>>>(b1, W2, att_src2, att_dst2);    // (4) <- ncu slot
    k_agg2<<<(NN + 7) / 8, 256>>>(b2, out);                       // (5)
}

// round 15
// speedup vs baseline: 1.0636x; 1.0636x over previous
#include <cuda_runtime.h>
#include <cuda_fp16.h>
#include <cstdint>

#define NN   50000
#define EE   1600000
#define FIN  512
#define F1   64        // H1*C1
#define NH1  8
#define C2   40
#define C2P  64        // padded h2 row (128B)
#define NBLK 196       // ceil(NN/256)
#define FULLM 0xffffffffu
#define LOG2E 1.4426950408889634f

// ------------------------- scratch (static device memory; no allocs allowed)
__device__ __half g_h1h[NN * F1];      // layer1 features, fp16 (gather payload)
__device__ __half g_as1h[NN * NH1];    // alpha_src1 * log2e, fp16
__device__ __half g_ad1h[NN * NH1];    // alpha_dst1 * log2e, fp16
__device__ __half g_h2hp[NN * C2P];    // layer2 linear out, fp16, 128B rows
__device__ float  g_as2[NN];
__device__ float  g_ad2[NN];
__device__ int    g_deg[NN];           // zero at entry of every call (k_zero restores)
__device__ int    g_rowptr[NN + 1];
__device__ int    g_cursor[NN];
__device__ int    g_col[EE];

__device__ __forceinline__ float leaky(float v) { return v > 0.f ? v : 0.2f * v; }

__device__ __forceinline__ uint32_t f2tf(float f) {
    uint32_t u;
    asm("cvt.rna.tf32.f32 %0, %1;" : "=r"(u) : "f"(f));
    return u;
}

__device__ __forceinline__ void mma_tf32(float* d, const uint32_t* a, const uint32_t* b) {
    asm volatile(
        "mma.sync.aligned.m16n8k8.row.col.f32.tf32.tf32.f32 "
        "{%0,%1,%2,%3}, {%4,%5,%6,%7}, {%8,%9}, {%0,%1,%2,%3};"
        : "+f"(d[0]), "+f"(d[1]), "+f"(d[2]), "+f"(d[3])
        : "r"(a[0]), "r"(a[1]), "r"(a[2]), "r"(a[3]), "r"(b[0]), "r"(b[1]));
}

__device__ __forceinline__ __half2 h2ex2(__half2 x) {
    __half2 r;
    asm("ex2.approx.f16x2 %0, %1;"
        : "=r"(*(uint32_t*)&r) : "r"(*(uint32_t*)&x));
    return r;
}
__device__ __forceinline__ __half2 u2h2(uint32_t u) { return *(__half2*)&u; }

// ------------------------- (side 1) degree histogram
__global__ void k_hist(const int* __restrict__ dst) {
    int e = blockIdx.x * blockDim.x + threadIdx.x;
    if (e < EE) atomicAdd(&g_deg[dst[e]], 1);
}

// ------------------------- (side 2) single-launch scan: rowptr/cursor
// (reads g_deg ONLY — reset happens in k_zero AFTER this kernel; no race)
__global__ __launch_bounds__(256) void k_scan1() {
    __shared__ int red[256];
    __shared__ int sm[256];
    __shared__ int sbase;
    const int b = blockIdx.x, t = threadIdx.x;
    const int base = b * 256;

    int pre = 0;
    for (int i = t; i < base; i += 256) pre += g_deg[i];
    red[t] = pre;
    __syncthreads();
#pragma unroll
    for (int off = 128; off > 0; off >>= 1) {
        if (t < off) red[t] += red[t + off];
        __syncthreads();
    }
    if (t == 0) sbase = red[0];

    const int i = base + t;
    const int d = (i < NN) ? g_deg[i] : 0;
    sm[t] = d;
    __syncthreads();
#pragma unroll
    for (int off = 1; off < 256; off <<= 1) {
        int v = (t >= off) ? sm[t - off] : 0;
        __syncthreads();
        sm[t] += v;
        __syncthreads();
    }
    const int bb = sbase;
    if (i < NN) {
        int rp = bb + sm[t] - d;
        g_rowptr[i] = rp;
        g_cursor[i] = rp;
    }
    if (b == NBLK - 1 && t == 255) g_rowptr[NN] = bb + sm[255];
}

// ------------------------- (side 3) reset g_deg for the NEXT call
// (runs after k_scan1 — kernel boundary guarantees all prefix reads are done)
__global__ void k_zero() {
    int i = blockIdx.x * blockDim.x + threadIdx.x;
    if (i < NN) g_deg[i] = 0;
}

// ------------------------- (side 4) edge scatter
__global__ void k_scatter(const int* __restrict__ src, const int* __restrict__ dst) {
    int e = blockIdx.x * blockDim.x + threadIdx.x;
    if (e < EE) {
        int d = dst[e];
        int p = atomicAdd(&g_cursor[d], 1);
        g_col[p] = src[e];
    }
}

// ------------------------- (main, slot 5... gemm) GEMM1 (tf32 TC) + fused att coeffs
__global__ __launch_bounds__(256) void k_gemm1(const float* __restrict__ x,
                                               const float* __restrict__ W1,
                                               const float* __restrict__ attS,
                                               const float* __restrict__ attD) {
    __shared__ float sA[128][36];
    __shared__ float sB[32][72];
    __shared__ float sAs[64], sAd[64];

    const int t    = threadIdx.x;
    const int wid  = t >> 5;
    const int lane = t & 31;
    const int m0   = blockIdx.x * 128;
    const int warp_m = (wid >> 1) * 32;
    const int warp_n = (wid & 1) * 32;
    if (t < 64) { sAs[t] = attS[t]; sAd[t] = attD[t]; }

    float acc[2][4][4];
#pragma unroll
    for (int mi = 0; mi < 2; mi++)
#pragma unroll
        for (int ni = 0; ni < 4; ni++)
#pragma unroll
            for (int e = 0; e < 4; e++) acc[mi][ni][e] = 0.f;

    const int r = lane >> 2;
    const int c = lane & 3;
    const int arow = t >> 3;
    const int acol = (t & 7) * 4;

    for (int kc = 0; kc < FIN; kc += 32) {
#pragma unroll
        for (int i = 0; i < 4; i++) {
            int row = i * 32 + arow;
            int gm  = m0 + row;
            float4 v = (gm < NN) ? *(const float4*)&x[(long)gm * FIN + kc + acol]
                                 : make_float4(0.f, 0.f, 0.f, 0.f);
            float4 tv;
            tv.x = __uint_as_float(f2tf(v.x));
            tv.y = __uint_as_float(f2tf(v.y));
            tv.z = __uint_as_float(f2tf(v.z));
            tv.w = __uint_as_float(f2tf(v.w));
            *(float4*)&sA[row][acol] = tv;
        }
#pragma unroll
        for (int i = 0; i < 2; i++) {
            int f   = t + i * 256;
            int row = f >> 4;
            int c4  = (f & 15) * 4;
            float4 v = *(const float4*)&W1[(kc + row) * F1 + c4];
            float4 tv;
            tv.x = __uint_as_float(f2tf(v.x));
            tv.y = __uint_as_float(f2tf(v.y));
            tv.z = __uint_as_float(f2tf(v.z));
            tv.w = __uint_as_float(f2tf(v.w));
            *(float4*)&sB[row][c4] = tv;
        }
        __syncthreads();

#pragma unroll
        for (int ks = 0; ks < 4; ks++) {
            const int k0 = ks * 8;
            uint32_t afrag[2][4];
#pragma unroll
            for (int mi = 0; mi < 2; mi++) {
                int mm = warp_m + mi * 16;
                afrag[mi][0] = __float_as_uint(sA[mm + r][k0 + c]);
                afrag[mi][1] = __float_as_uint(sA[mm + r + 8][k0 + c]);
                afrag[mi][2] = __float_as_uint(sA[mm + r][k0 + c + 4]);
                afrag[mi][3] = __float_as_uint(sA[mm + r + 8][k0 + c + 4]);
            }
            uint32_t bfrag[4][2];
#pragma unroll
            for (int ni = 0; ni < 4; ni++) {
                int nn = warp_n + ni * 8;
                bfrag[ni][0] = __float_as_uint(sB[k0 + c][nn + r]);
                bfrag[ni][1] = __float_as_uint(sB[k0 + c + 4][nn + r]);
            }
#pragma unroll
            for (int mi = 0; mi < 2; mi++)
#pragma unroll
                for (int ni = 0; ni < 4; ni++)
                    mma_tf32(acc[mi][ni], afrag[mi], bfrag[ni]);
        }
        __syncthreads();
    }

#pragma unroll
    for (int mi = 0; mi < 2; mi++) {
        int row_g = m0 + warp_m + mi * 16 + r;
        int row_h = row_g + 8;
#pragma unroll
        for (int ni = 0; ni < 4; ni++) {
            int nn = warp_n + ni * 8;
            int col = nn + c * 2;
            if (row_g < NN)
                *(__half2*)&g_h1h[row_g * F1 + col] = __floats2half2_rn(acc[mi][ni][0], acc[mi][ni][1]);
            if (row_h < NN)
                *(__half2*)&g_h1h[row_h * F1 + col] = __floats2half2_rn(acc[mi][ni][2], acc[mi][ni][3]);
            float as0 = sAs[col], as1v = sAs[col + 1];
            float ad0 = sAd[col], ad1v = sAd[col + 1];
            float psg = acc[mi][ni][0] * as0 + acc[mi][ni][1] * as1v;
            float pdg = acc[mi][ni][0] * ad0 + acc[mi][ni][1] * ad1v;
            float psh = acc[mi][ni][2] * as0 + acc[mi][ni][3] * as1v;
            float pdh = acc[mi][ni][2] * ad0 + acc[mi][ni][3] * ad1v;
#pragma unroll
            for (int off = 1; off <= 2; off <<= 1) {
                psg += __shfl_xor_sync(FULLM, psg, off);
                pdg += __shfl_xor_sync(FULLM, pdg, off);
                psh += __shfl_xor_sync(FULLM, psh, off);
                pdh += __shfl_xor_sync(FULLM, pdh, off);
            }
            int h = nn >> 3;
            if (c == 0) {
                if (row_g < NN) {
                    g_as1h[row_g * NH1 + h] = __float2half_rn(psg * LOG2E);
                    g_ad1h[row_g * NH1 + h] = __float2half_rn(pdg * LOG2E);
                }
                if (row_h < NN) {
                    g_as1h[row_h * NH1 + h] = __float2half_rn(psh * LOG2E);
                    g_ad1h[row_h * NH1 + h] = __float2half_rn(pdh * LOG2E);
                }
            }
        }
    }
}

// ------------------------- layer-1 aggregation + fused layer-2 linear/att
// one warp per dst node; 8-wide batched gathers (R10-proven form)
__global__ __launch_bounds__(256) void k_agg1(const float* __restrict__ b1,
                                              const float* __restrict__ W2,
                                              const float* __restrict__ att_s,
                                              const float* __restrict__ att_d) {
    __shared__ float swt[8][8][36];
    __shared__ int   ssrc[8][32];
    __shared__ float sW2[F1 * C2];
    __shared__ float sAs2[C2], sAd2[C2];

    for (int idx = threadIdx.x; idx < F1 * C2; idx += 256) sW2[idx] = W2[idx];
    if (threadIdx.x < C2) {
        sAs2[threadIdx.x] = att_s[threadIdx.x];
        sAd2[threadIdx.x] = att_d[threadIdx.x];
    }
    __syncthreads();

    const int w    = threadIdx.x >> 5;
    const int lane = threadIdx.x & 31;
    const int node = blockIdx.x * 8 + w;
    if (node >= NN) return;
    const int beg   = g_rowptr[node];
    const int deg   = g_rowptr[node + 1] - beg;
    const int total = deg + 1;

    const __half2 k02 = __floats2half2_rn(0.2f, 0.2f);
    int4 adv = *(const int4*)&g_ad1h[node * NH1];
    __half2 adp[4] = { u2h2(adv.x), u2h2(adv.y), u2h2(adv.z), u2h2(adv.w) };

    const int hl = lane >> 2;
    const int c0 = lane * 2;
    float acc0 = 0.f, acc1 = 0.f;
    float ssum[8];
#pragma unroll
    for (int h = 0; h < 8; h++) ssum[h] = 0.f;

    for (int k0 = 0; k0 < total; k0 += 32) {
        int kk  = k0 + lane;
        int lim = min(32, total - k0);
        __syncwarp();
        if (kk < total) {
            int srcn = (kk < deg) ? g_col[beg + kk] : node;
            int4 sv = *(const int4*)&g_as1h[srcn * NH1];
            __half2 sp[4] = { u2h2(sv.x), u2h2(sv.y), u2h2(sv.z), u2h2(sv.w) };
#pragma unroll
            for (int p = 0; p < 4; p++) {
                __half2 l = __hadd2(sp[p], adp[p]);                  // (as+ad)*log2e
                __half2 lk = __hmax2(l, __hmul2(l, k02));            // leaky (exact)
                float2 f = __half22float2(h2ex2(lk));                // exp via ex2
                ssum[2 * p]     += f.x;
                ssum[2 * p + 1] += f.y;
                swt[w][2 * p][lane]     = f.x;
                swt[w][2 * p + 1][lane] = f.y;
            }
            ssrc[w][lane] = srcn;
        }
        __syncwarp();
        // 8-wide batched gather: force 8 independent LDGs in flight
        int j = 0;
        for (; j + 8 <= lim; j += 8) {
            int   sn[8];
            float wt[8];
            float2 pv[8];
#pragma unroll
            for (int q = 0; q < 8; q++) {
                sn[q] = ssrc[w][j + q];
                wt[q] = swt[w][hl][j + q];
            }
#pragma unroll
            for (int q = 0; q < 8; q++)
                pv[q] = __half22float2(*(const __half2*)&g_h1h[sn[q] * F1 + c0]);
#pragma unroll
            for (int q = 0; q < 8; q++) {
                acc0 += wt[q] * pv[q].x;
                acc1 += wt[q] * pv[q].y;
            }
        }
        for (; j < lim; j++) {
            int srcn = ssrc[w][j];
            float wt = swt[w][hl][j];
            float2 hv = __half22float2(*(const __half2*)&g_h1h[srcn * F1 + c0]);
            acc0 += wt * hv.x;
            acc1 += wt * hv.y;
        }
    }
#pragma unroll
    for (int h = 0; h < 8; h++) {
#pragma unroll
        for (int off = 16; off > 0; off >>= 1)
            ssum[h] += __shfl_xor_sync(FULLM, ssum[h], off);
    }
    float myS = 0.f;
#pragma unroll
    for (int h = 0; h < 8; h++)
        if (hl == h) myS = ssum[h];
    float inv = __fdividef(1.0f, myS);

    // x2 row in registers (relu + bias)
    float v0 = fmaxf(acc0 * inv + b1[c0], 0.f);
    float v1 = fmaxf(acc1 * inv + b1[c0 + 1], 0.f);

    // fused layer-2 linear: h2 = x2 @ W2  (+ attention coefficients)
    const int cA = lane;
    const int cB = lane + 32;
    const bool has1 = (lane < 8);
    float a0 = 0.f, a1 = 0.f;
#pragma unroll
    for (int kk = 0; kk < 32; kk++) {
        float x0 = __shfl_sync(FULLM, v0, kk);
        float x1 = __shfl_sync(FULLM, v1, kk);
        a0 += x0 * sW2[(2 * kk) * C2 + cA] + x1 * sW2[(2 * kk + 1) * C2 + cA];
        if (has1)
            a1 += x0 * sW2[(2 * kk) * C2 + cB] + x1 * sW2[(2 * kk + 1) * C2 + cB];
    }
    g_h2hp[node * C2P + cA] = __float2half_rn(a0);
    if (has1) g_h2hp[node * C2P + cB] = __float2half_rn(a1);

    float ps = a0 * sAs2[cA] + (has1 ? a1 * sAs2[cB] : 0.f);
    float pd = a0 * sAd2[cA] + (has1 ? a1 * sAd2[cB] : 0.f);
#pragma unroll
    for (int off = 16; off > 0; off >>= 1) {
        ps += __shfl_xor_sync(FULLM, ps, off);
        pd += __shfl_xor_sync(FULLM, pd, off);
    }
    if (lane == 0) { g_as2[node] = ps; g_ad2[node] = pd; }
}

// ------------------------- layer-2 aggregation + bias + log_softmax
// one warp per node; 20 lanes own channel PAIRS; 8-wide batched gathers
__global__ __launch_bounds__(256) void k_agg2(const float* __restrict__ b2,
                                              float* __restrict__ out) {
    __shared__ float swt[8][32];
    __shared__ int   ssrc[8][32];
    const int w    = threadIdx.x >> 5;
    const int lane = threadIdx.x & 31;
    const int node = blockIdx.x * 8 + w;
    if (node >= NN) return;
    const int beg   = g_rowptr[node];
    const int deg   = g_rowptr[node + 1] - beg;
    const int total = deg + 1;
    const float adn = g_ad2[node];

    const bool active = (lane < 20);        // channel pair 2*lane, 2*lane+1
    const int cp = lane * 2;
    float acc0 = 0.f, acc1 = 0.f, ssum = 0.f;
    for (int k0 = 0; k0 < total; k0 += 32) {
        int kk  = k0 + lane;
        int lim = min(32, total - k0);
        __syncwarp();
        if (kk < total) {
            int srcn = (kk < deg) ? g_col[beg + kk] : node;
            float wt = __expf(leaky(g_as2[srcn] + adn));
            ssum += wt;
            swt[w][lane]  = wt;
            ssrc[w][lane] = srcn;
        }
        __syncwarp();
        if (active) {
            int j = 0;
            for (; j + 8 <= lim; j += 8) {
                int   sn[8];
                float wt[8];
                float2 pv[8];
#pragma unroll
                for (int q = 0; q < 8; q++) {
                    sn[q] = ssrc[w][j + q];
                    wt[q] = swt[w][j + q];
                }
#pragma unroll
                for (int q = 0; q < 8; q++)
                    pv[q] = __half22float2(*(const __half2*)&g_h2hp[sn[q] * C2P + cp]);
#pragma unroll
                for (int q = 0; q < 8; q++) {
                    acc0 += wt[q] * pv[q].x;
                    acc1 += wt[q] * pv[q].y;
                }
            }
            for (; j < lim; j++) {
                int srcn = ssrc[w][j];
                float wt = swt[w][j];
                float2 hv = __half22float2(*(const __half2*)&g_h2hp[srcn * C2P + cp]);
                acc0 += wt * hv.x;
                acc1 += wt * hv.y;
            }
        }
    }
#pragma unroll
    for (int off = 16; off > 0; off >>= 1)
        ssum += __shfl_xor_sync(FULLM, ssum, off);
    float inv = __fdividef(1.0f, ssum);

    float o0 = active ? (acc0 * inv + b2[cp])     : -1e30f;
    float o1 = active ? (acc1 * inv + b2[cp + 1]) : -1e30f;

    float mx = fmaxf(o0, o1);
#pragma unroll
    for (int off = 16; off > 0; off >>= 1)
        mx = fmaxf(mx, __shfl_xor_sync(FULLM, mx, off));
    float se = active ? (__expf(o0 - mx) + __expf(o1 - mx)) : 0.f;
#pragma unroll
    for (int off = 16; off > 0; off >>= 1)
        se += __shfl_xor_sync(FULLM, se, off);
    float lse = mx + __logf(se);

    if (active)
        *(float2*)&out[node * C2 + cp] = make_float2(o0 - lse, o1 - lse);
}

// ------------------------- launch: CSR chain on side stream || GEMM1 on main
extern "C" void kernel_launch(void* const* d_in, const int* in_sizes, int n_in,
                              void* d_out, int out_size) {
    const float* x        = (const float*)d_in[0];
    const int*   ei       = (const int*)d_in[1];
    const float* W1       = (const float*)d_in[2];
    const float* att_src1 = (const float*)d_in[3];
    const float* att_dst1 = (const float*)d_in[4];
    const float* b1       = (const float*)d_in[5];
    const float* W2       = (const float*)d_in[6];
    const float* att_src2 = (const float*)d_in[7];
    const float* att_dst2 = (const float*)d_in[8];
    const float* b2       = (const float*)d_in[9];
    float* out = (float*)d_out;

    const int* src = ei;
    const int* dst = ei + EE;

    static cudaStream_t s_csr = nullptr;
    static cudaEvent_t  e_fork = nullptr, e_join = nullptr;
    if (s_csr == nullptr) {
        cudaStreamCreateWithFlags(&s_csr, cudaStreamNonBlocking);
        cudaEventCreateWithFlags(&e_fork, cudaEventDisableTiming);
        cudaEventCreateWithFlags(&e_join, cudaEventDisableTiming);
    }

    // fork: CSR build on side stream (4 kernels, race-free ordering)
    cudaEventRecord(e_fork, 0);
    cudaStreamWaitEvent(s_csr, e_fork, 0);
    k_hist<<<(EE + 255) / 256, 256, 0, s_csr>>>(dst);              // 1
    k_scan1<<<NBLK, 256, 0, s_csr>>>();                            // 2 (reads g_deg)
    k_zero<<<(NN + 255) / 256, 256, 0, s_csr>>>();                 // 3 (reset AFTER all reads)
    k_scatter<<<(EE + 255) / 256, 256, 0, s_csr>>>(src, dst);      // 4
    cudaEventRecord(e_join, s_csr);

    // concurrent on main: layer-1 GEMM
    k_gemm1<<<(NN + 127) / 128, 256>>>(x, W1, att_src1, att_dst1); // 5

    // join: aggregation needs both CSR and GEMM1
    cudaStreamWaitEvent(0, e_join, 0);

    k_agg1<<<(NN + 7) / 8, 256>>>(b1, W2, att_src2, att_dst2);     // 6
    k_agg2<<<(NN + 7) / 8, 256>>>(b2, out);                        // 7
}